// round 1
// baseline (speedup 1.0000x reference)
#include <cuda_runtime.h>
#include <math.h>

// Problem constants
#define SEQ 1024
#define DIM 128
#define NBM 8      // B*M
#define NHEAD 8    // heads per (b,m)
#define NG 64      // total heads = NBM*NHEAD

// Scratch (static device globals; no dynamic allocation allowed)
__device__ float g_qh[(size_t)NG * SEQ * DIM];
__device__ float g_kh[(size_t)NG * SEQ * DIM];
__device__ float g_vh[(size_t)NG * SEQ * DIM];
__device__ float g_oh[(size_t)NG * SEQ * DIM];

// ---------------------------------------------------------------------------
// Kernel 1: projections.  For each (mat in {q,k,v}, bm in 0..7):
//   Y[s, e] = sum_c X[bm, s, c] * W[m, c, e],  e = h*128 + d
// stored head-split:  g_Xh[((bm*8 + h)*1024 + s)*128 + d]
// Classic 128x128 tile SGEMM, BK=8, 256 threads, 8x8 per-thread microtile.
// blockIdx.x = head (BN=128 == D so one head per col-tile), .y = s-tile, .z = 24 gemms
// ---------------------------------------------------------------------------
__global__ void __launch_bounds__(256, 2) proj_kernel(
    const float* __restrict__ q, const float* __restrict__ k, const float* __restrict__ v,
    const float* __restrict__ Wq, const float* __restrict__ Wk, const float* __restrict__ Wv)
{
    __shared__ float As[8][132];   // [k][row], padded
    __shared__ float Bs[8][128];   // [k][col]

    const int z   = blockIdx.z;
    const int mat = z >> 3;
    const int bm  = z & 7;
    const int m   = bm & 3;

    const float* X = (mat == 0 ? q : mat == 1 ? k : v) + (size_t)bm * SEQ * DIM;
    const float* W = (mat == 0 ? Wq : mat == 1 ? Wk : Wv) + (size_t)m * DIM * (NHEAD * DIM);
    float*       Y = (mat == 0 ? g_qh : mat == 1 ? g_kh : g_vh) + (size_t)bm * NHEAD * SEQ * DIM;

    const int tid = threadIdx.x;
    const int ty  = tid >> 4;        // 0..15
    const int tx  = tid & 15;        // 0..15
    const int bx  = blockIdx.x;      // head 0..7
    const int by  = blockIdx.y;      // s-tile 0..7

    const int arow = tid >> 1;             // 0..127
    const int ak   = (tid & 1) * 4;        // 0 or 4
    const int brow = tid >> 5;             // 0..7
    const int bc   = (tid & 31) * 4;       // 0..124

    float acc[8][8];
#pragma unroll
    for (int i = 0; i < 8; i++)
#pragma unroll
        for (int j = 0; j < 8; j++) acc[i][j] = 0.f;

    for (int k0 = 0; k0 < DIM; k0 += 8) {
        float4 av = *(const float4*)(X + (size_t)(by * 128 + arow) * DIM + k0 + ak);
        float4 bv = *(const float4*)(W + (size_t)(k0 + brow) * (NHEAD * DIM) + bx * 128 + bc);
        __syncthreads();
        As[ak + 0][arow] = av.x;
        As[ak + 1][arow] = av.y;
        As[ak + 2][arow] = av.z;
        As[ak + 3][arow] = av.w;
        *(float4*)&Bs[brow][bc] = bv;
        __syncthreads();
#pragma unroll
        for (int kk = 0; kk < 8; kk++) {
            float4 a0 = *(const float4*)&As[kk][ty * 8];
            float4 a1 = *(const float4*)&As[kk][ty * 8 + 4];
            float4 b0 = *(const float4*)&Bs[kk][tx * 8];
            float4 b1 = *(const float4*)&Bs[kk][tx * 8 + 4];
            float a[8] = {a0.x, a0.y, a0.z, a0.w, a1.x, a1.y, a1.z, a1.w};
            float b[8] = {b0.x, b0.y, b0.z, b0.w, b1.x, b1.y, b1.z, b1.w};
#pragma unroll
            for (int i = 0; i < 8; i++)
#pragma unroll
                for (int j = 0; j < 8; j++)
                    acc[i][j] = fmaf(a[i], b[j], acc[i][j]);
        }
    }

#pragma unroll
    for (int i = 0; i < 8; i++) {
        int s = by * 128 + ty * 8 + i;
        float* dst = Y + ((size_t)bx * SEQ + s) * DIM + tx * 8;
        *(float4*)(dst)     = make_float4(acc[i][0], acc[i][1], acc[i][2], acc[i][3]);
        *(float4*)(dst + 4) = make_float4(acc[i][4], acc[i][5], acc[i][6], acc[i][7]);
    }
}

// ---------------------------------------------------------------------------
// Kernel 2: flash attention per head, fp32, online softmax.
// Block = (head g, q-tile of 64 rows), 512 threads (16 warps).
// Q kept in smem transposed (d-major) so QK^T fragment loads are conflict-free;
// K/V row-major; P staged in smem between S-phase and PV-phase.
// grid = (16, 64)
// ---------------------------------------------------------------------------
#define QTS_STRIDE 66
#define PS_STRIDE  68
#define QTS_F (DIM * QTS_STRIDE)          // 8448
#define KS_F  (64 * DIM)                  // 8192
#define VS_F  (64 * DIM)                  // 8192
#define PS_F  (64 * PS_STRIDE)            // 4352
#define ATTN_SMEM_BYTES ((QTS_F + KS_F + VS_F + PS_F + 192) * 4)   // 117504

__global__ void __launch_bounds__(512, 1) attn_kernel()
{
    extern __shared__ float smf[];
    float* qts  = smf;                 // [d][r] transposed, stride 66
    float* ks   = qts + QTS_F;         // [c][d]
    float* vs   = ks + KS_F;           // [c][d]
    float* ps   = vs + VS_F;           // [r][c], stride 68
    float* rowm = ps + PS_F;
    float* rowl = rowm + 64;
    float* rowc = rowl + 64;

    const int g    = blockIdx.y;       // head 0..63
    const int qt   = blockIdx.x;       // 0..15
    const int tid  = threadIdx.x;
    const int warp = tid >> 5;
    const int lane = tid & 31;

    const float scale = 0.08838834764831845f;   // 1/sqrt(128)

    const float* Qg = g_qh + ((size_t)g * SEQ + qt * 64) * DIM;
    const float* Kg = g_kh + (size_t)g * SEQ * DIM;
    const float* Vg = g_vh + (size_t)g * SEQ * DIM;

    // Load Q tile transposed (pre-scaled)
#pragma unroll
    for (int it = 0; it < 4; it++) {
        int idx = tid + it * 512;
        int r   = idx >> 5;
        int d4  = (idx & 31) * 4;
        float4 qv = *(const float4*)(Qg + (size_t)r * DIM + d4);
        qts[(d4 + 0) * QTS_STRIDE + r] = qv.x * scale;
        qts[(d4 + 1) * QTS_STRIDE + r] = qv.y * scale;
        qts[(d4 + 2) * QTS_STRIDE + r] = qv.z * scale;
        qts[(d4 + 3) * QTS_STRIDE + r] = qv.w * scale;
    }
    if (tid < 64) { rowm[tid] = -1e30f; rowl[tid] = 0.f; }

    float o[4][4];
#pragma unroll
    for (int i = 0; i < 4; i++)
#pragma unroll
        for (int j = 0; j < 4; j++) o[i][j] = 0.f;

    const int sr0 = lane * 2;   // S rows owned in S-phase
    const int sc0 = warp * 4;   // S cols owned in S-phase
    const int pr0 = warp * 4;   // O rows owned in PV-phase
    const int pd  = lane * 4;   // O cols owned in PV-phase

    for (int t = 0; t < 16; t++) {
        __syncthreads();   // prior PV done with vs/ps
        // Load K/V tile (coalesced)
#pragma unroll
        for (int it = 0; it < 4; it++) {
            int idx = tid + it * 512;
            int r   = idx >> 5;
            int d4  = (idx & 31) * 4;
            *(float4*)(ks + r * DIM + d4) = *(const float4*)(Kg + (size_t)(t * 64 + r) * DIM + d4);
            *(float4*)(vs + r * DIM + d4) = *(const float4*)(Vg + (size_t)(t * 64 + r) * DIM + d4);
        }
        __syncthreads();

        // ---- S = (Q*scale) K^T : each thread 2 rows x 4 cols ----
        float acc[2][4];
#pragma unroll
        for (int i = 0; i < 2; i++)
#pragma unroll
            for (int j = 0; j < 4; j++) acc[i][j] = 0.f;

#pragma unroll 8
        for (int d = 0; d < DIM; d += 4) {
            float4 kf[4];
#pragma unroll
            for (int j = 0; j < 4; j++)
                kf[j] = *(const float4*)(ks + (sc0 + j) * DIM + d);   // warp-uniform (broadcast)
#pragma unroll
            for (int dd = 0; dd < 4; dd++) {
                float2 q2 = *(const float2*)(qts + (d + dd) * QTS_STRIDE + sr0);
#pragma unroll
                for (int j = 0; j < 4; j++) {
                    float kv = ((const float*)&kf[j])[dd];
                    acc[0][j] = fmaf(q2.x, kv, acc[0][j]);
                    acc[1][j] = fmaf(q2.y, kv, acc[1][j]);
                }
            }
        }
#pragma unroll
        for (int i = 0; i < 2; i++)
#pragma unroll
            for (int j = 0; j < 4; j++)
                ps[(sr0 + i) * PS_STRIDE + sc0 + j] = acc[i][j];
        __syncthreads();

        // ---- online softmax stats: 8 threads per row ----
        {
            int rr  = tid >> 3;
            int sub = tid & 7;
            float* prow = ps + rr * PS_STRIDE + sub * 8;
            float m_old = rowm[rr];
            float mx = -1e30f;
#pragma unroll
            for (int j = 0; j < 8; j++) mx = fmaxf(mx, prow[j]);
#pragma unroll
            for (int off = 4; off > 0; off >>= 1)
                mx = fmaxf(mx, __shfl_xor_sync(0xffffffffu, mx, off));
            float m_new = fmaxf(m_old, mx);
            float corr  = __expf(m_old - m_new);
            float sum = 0.f;
#pragma unroll
            for (int j = 0; j < 8; j++) {
                float p = __expf(prow[j] - m_new);
                prow[j] = p;
                sum += p;
            }
#pragma unroll
            for (int off = 4; off > 0; off >>= 1)
                sum += __shfl_xor_sync(0xffffffffu, sum, off);
            if (sub == 0) {
                rowm[rr] = m_new;
                rowl[rr] = rowl[rr] * corr + sum;
                rowc[rr] = corr;
            }
        }
        __syncthreads();

        // ---- O = O*corr + P @ V : each thread 4 rows x 4 cols ----
        {
#pragma unroll
            for (int i = 0; i < 4; i++) {
                float cr = rowc[pr0 + i];
#pragma unroll
                for (int j = 0; j < 4; j++) o[i][j] *= cr;
            }
#pragma unroll
            for (int c = 0; c < 64; c += 4) {
                float4 pf[4];
#pragma unroll
                for (int i = 0; i < 4; i++)
                    pf[i] = *(const float4*)(ps + (pr0 + i) * PS_STRIDE + c);  // warp-uniform
#pragma unroll
                for (int cc = 0; cc < 4; cc++) {
                    float4 vv = *(const float4*)(vs + (c + cc) * DIM + pd);
#pragma unroll
                    for (int i = 0; i < 4; i++) {
                        float pw = ((const float*)&pf[i])[cc];
                        o[i][0] = fmaf(pw, vv.x, o[i][0]);
                        o[i][1] = fmaf(pw, vv.y, o[i][1]);
                        o[i][2] = fmaf(pw, vv.z, o[i][2]);
                        o[i][3] = fmaf(pw, vv.w, o[i][3]);
                    }
                }
            }
        }
    }

    // Epilogue: normalize and store per-head output
    float* Og = g_oh + ((size_t)g * SEQ + qt * 64) * DIM;
#pragma unroll
    for (int i = 0; i < 4; i++) {
        float inv = 1.0f / rowl[pr0 + i];
        *(float4*)(Og + (size_t)(pr0 + i) * DIM + pd) =
            make_float4(o[i][0] * inv, o[i][1] * inv, o[i][2] * inv, o[i][3] * inv);
    }
}

// ---------------------------------------------------------------------------
// Kernel 3: mean over heads + residual.  out[bm,s,d] = q[bm,s,d] + mean_h oh
// One float4 per thread: 262144 threads.
// ---------------------------------------------------------------------------
__global__ void __launch_bounds__(256) reduce_kernel(const float* __restrict__ q,
                                                     float* __restrict__ out)
{
    int i4 = blockIdx.x * 256 + threadIdx.x;    // 0..262143
    int bm = i4 >> 15;                           // / 32768 float4 per (b,m)
    int r4 = i4 & 32767;
    const float4* oh4 = (const float4*)g_oh;
    float sx = 0.f, sy = 0.f, sz = 0.f, sw = 0.f;
#pragma unroll
    for (int h = 0; h < NHEAD; h++) {
        float4 t = oh4[(size_t)(bm * NHEAD + h) * 32768 + r4];
        sx += t.x; sy += t.y; sz += t.z; sw += t.w;
    }
    float4 qv = ((const float4*)q)[i4];
    ((float4*)out)[i4] = make_float4(qv.x + 0.125f * sx, qv.y + 0.125f * sy,
                                     qv.z + 0.125f * sz, qv.w + 0.125f * sw);
}

// ---------------------------------------------------------------------------
extern "C" void kernel_launch(void* const* d_in, const int* in_sizes, int n_in,
                              void* d_out, int out_size)
{
    const float* q  = (const float*)d_in[0];
    const float* k  = (const float*)d_in[1];
    const float* v  = (const float*)d_in[2];
    const float* Wq = (const float*)d_in[3];
    const float* Wk = (const float*)d_in[4];
    const float* Wv = (const float*)d_in[5];
    float* out = (float*)d_out;

    cudaFuncSetAttribute(attn_kernel, cudaFuncAttributeMaxDynamicSharedMemorySize,
                         ATTN_SMEM_BYTES);

    proj_kernel<<<dim3(8, 8, 24), 256>>>(q, k, v, Wq, Wk, Wv);
    attn_kernel<<<dim3(16, 64), 512, ATTN_SMEM_BYTES>>>();
    reduce_kernel<<<1024, 256>>>(q, out);
}